// round 15
// baseline (speedup 1.0000x reference)
#include <cuda_runtime.h>
#include <cuda_fp16.h>
#include <cstdint>

#define N_TOK 2304
#define BATCH 4
#define HEADS 8
#define DHEAD 32
#define HIDDEN 256
#define QSCALE 0.17677669529663689f  // 32^-0.5
#define LOG2E  1.4426950408889634f
#define ONES2  0x3C003C00u           // f16x2 (1.0, 1.0)

// ---- fp16 helpers ----
__device__ __forceinline__ uint32_t h2pk(float lo, float hi) {
    uint32_t r; asm("cvt.rn.f16x2.f32 %0,%1,%2;" : "=r"(r) : "f"(hi), "f"(lo)); return r;
}
__device__ __forceinline__ uint32_t ex2h2(uint32_t x) {
    uint32_t r; asm("ex2.approx.f16x2 %0,%1;" : "=r"(r) : "r"(x)); return r;
}
__device__ __forceinline__ void mma_f16(float c[4], const uint32_t a[4],
                                        uint32_t b0, uint32_t b1) {
    asm("mma.sync.aligned.m16n8k16.row.col.f32.f16.f16.f32 "
        "{%0,%1,%2,%3},{%4,%5,%6,%7},{%8,%9},{%0,%1,%2,%3};"
        : "+f"(c[0]), "+f"(c[1]), "+f"(c[2]), "+f"(c[3])
        : "r"(a[0]), "r"(a[1]), "r"(a[2]), "r"(a[3]), "r"(b0), "r"(b1));
}
__device__ __forceinline__ void ldmx4t(uint32_t r[4], uint32_t addr) {
    asm volatile("ldmatrix.sync.aligned.m8n8.x4.trans.shared.b16 {%0,%1,%2,%3},[%4];"
                 : "=r"(r[0]), "=r"(r[1]), "=r"(r[2]), "=r"(r[3]) : "r"(addr));
}

// ---- cp.async helpers ----
__device__ __forceinline__ void cpa16(uint32_t smem_dst, const void* gsrc) {
    asm volatile("cp.async.cg.shared.global [%0],[%1],16;" :: "r"(smem_dst), "l"(gsrc));
}
__device__ __forceinline__ void cpa_commit() { asm volatile("cp.async.commit_group;"); }
__device__ __forceinline__ void cpa_wait1()  { asm volatile("cp.async.wait_group 1;"); }
__device__ __forceinline__ void cpa_wait0()  { asm volatile("cp.async.wait_group 0;"); }

// Scratch (alloc-free rule: __device__ globals)
__device__ __half g_xh   [BATCH * 256 * N_TOK];          // fp16 x
__device__ __half g_wqkvh[3 * HIDDEN * 256];             // fp16 w_qkv
__device__ __half g_wouth[HIDDEN * 256];                 // fp16 w_out
__device__ __half g_qkvh [BATCH * 3 * HIDDEN * N_TOK];   // fp16 qkv
__device__ __half g_aoh  [BATCH * HIDDEN * N_TOK];       // fp16 attn out

// ---------------------------------------------------------------------------
// f32 -> f16 conversion for x, w_qkv, w_out (single launch)
// ---------------------------------------------------------------------------
__global__ __launch_bounds__(256)
void f2h3(const float* __restrict__ a0, __half* __restrict__ o0, int n0,
          const float* __restrict__ a1, __half* __restrict__ o1, int n1,
          const float* __restrict__ a2, __half* __restrict__ o2, int n2)
{
    int i = (blockIdx.x * 256 + threadIdx.x) * 4;
    const float* src; __half* dst;
    if (i < n0)            { src = a0 + i;           dst = o0 + i; }
    else if (i < n0 + n1)  { src = a1 + (i - n0);    dst = o1 + (i - n0); }
    else if (i < n0 + n1 + n2) { src = a2 + (i - n0 - n1); dst = o2 + (i - n0 - n1); }
    else return;
    float4 v = *(const float4*)src;
    *(uint2*)dst = make_uint2(h2pk(v.x, v.y), h2pk(v.z, v.w));
}

// ---------------------------------------------------------------------------
// all-fp16 GEMM (R14-proven): 128m x 128j CTA tile, K in 8 chunks of 32,
// cp.async double-buffered, W A-fragments prefetched one chunk ahead.
// ---------------------------------------------------------------------------
#define HPG 136

__global__ __launch_bounds__(256)
void gemm_h(const __half* __restrict__ W, const __half* __restrict__ X,
            void* __restrict__ Yv, int M,
            const float* __restrict__ bias, int qscale, int out_half)
{
    __shared__ __align__(16) uint16_t sX[2][32 * HPG];

    const int b  = blockIdx.z;
    const int m0 = blockIdx.y * 128;
    const int j0 = blockIdx.x * 128;
    const int tid = threadIdx.x;
    const int lane = tid & 31, warp = tid >> 5;
    const int g = lane >> 2, tg = lane & 3;
    const int mw = m0 + 16 * warp;

    const __half* Xb = X + (size_t)b * 256 * N_TOK;
    const uint32_t sbase = (uint32_t)__cvta_generic_to_shared(sX);

    int skk[2], sj8[2];
#pragma unroll
    for (int l = 0; l < 2; l++) {
        int t = tid + l * 256;
        skk[l] = t >> 4; sj8[l] = (t & 15) * 8;
    }

    float acc[16][4];
#pragma unroll
    for (int nt = 0; nt < 16; nt++)
#pragma unroll
        for (int c = 0; c < 4; c++) acc[nt][c] = 0.f;

#pragma unroll
    for (int l = 0; l < 2; l++)
        cpa16(sbase + (uint32_t)(skk[l] * HPG + sj8[l]) * 2,
              Xb + (size_t)skk[l] * N_TOK + j0 + sj8[l]);
    cpa_commit();

    uint32_t aw[2][4];
#pragma unroll
    for (int kc = 0; kc < 2; kc++) {
        const __half* wr = W + (size_t)(mw + g) * 256 + kc * 16;
        aw[kc][0] = *(const uint32_t*)(wr + 2 * tg);
        aw[kc][1] = *(const uint32_t*)(wr + 8 * 256 + 2 * tg);
        aw[kc][2] = *(const uint32_t*)(wr + 2 * tg + 8);
        aw[kc][3] = *(const uint32_t*)(wr + 8 * 256 + 2 * tg + 8);
    }

    for (int c = 0; c < 8; c++) {
        if (c > 0) __syncthreads();
        if (c + 1 < 8) {
            const int kn = (c + 1) * 32;
            const uint32_t boff = (uint32_t)(((c + 1) & 1) * 32 * HPG) * 2;
#pragma unroll
            for (int l = 0; l < 2; l++)
                cpa16(sbase + boff + (uint32_t)(skk[l] * HPG + sj8[l]) * 2,
                      Xb + (size_t)(kn + skk[l]) * N_TOK + j0 + sj8[l]);
            cpa_commit();
        }

        uint32_t an[2][4];
        if (c + 1 < 8) {
#pragma unroll
            for (int kc = 0; kc < 2; kc++) {
                const __half* wr = W + (size_t)(mw + g) * 256 + (c + 1) * 32 + kc * 16;
                an[kc][0] = *(const uint32_t*)(wr + 2 * tg);
                an[kc][1] = *(const uint32_t*)(wr + 8 * 256 + 2 * tg);
                an[kc][2] = *(const uint32_t*)(wr + 2 * tg + 8);
                an[kc][3] = *(const uint32_t*)(wr + 8 * 256 + 2 * tg + 8);
            }
        }

        if (c + 1 < 8) cpa_wait1(); else cpa_wait0();
        __syncthreads();

        const uint32_t xaddr0 = sbase + (uint32_t)((c & 1) * 32 * HPG + lane * HPG) * 2;
#pragma unroll
        for (int nt = 0; nt < 16; nt++) {
            uint32_t kf[4];
            ldmx4t(kf, xaddr0 + (uint32_t)nt * 16);
            mma_f16(acc[nt], aw[0], kf[0], kf[1]);
            mma_f16(acc[nt], aw[1], kf[2], kf[3]);
        }
        if (c + 1 < 8) {
#pragma unroll
            for (int kc = 0; kc < 2; kc++)
#pragma unroll
                for (int q = 0; q < 4; q++) aw[kc][q] = an[kc][q];
        }
    }

    const int mr0 = mw + g, mr1 = mw + g + 8;
    if (out_half) {
        const float qs = QSCALE * LOG2E;
        const float s0 = (qscale && mr0 < HIDDEN) ? qs : 1.f;
        const float s1 = (qscale && mr1 < HIDDEN) ? qs : 1.f;
        __half* Yh = (__half*)Yv;
        __half* y0 = Yh + ((size_t)b * M + mr0) * N_TOK + j0 + 2 * tg;
        __half* y1 = Yh + ((size_t)b * M + mr1) * N_TOK + j0 + 2 * tg;
#pragma unroll
        for (int nt = 0; nt < 16; nt++) {
            *(uint32_t*)(y0 + nt * 8) = h2pk(acc[nt][0] * s0, acc[nt][1] * s0);
            *(uint32_t*)(y1 + nt * 8) = h2pk(acc[nt][2] * s1, acc[nt][3] * s1);
        }
    } else {
        float* Yf = (float*)Yv;
        const float bv0 = bias ? bias[mr0] : 0.f;
        const float bv1 = bias ? bias[mr1] : 0.f;
        float* y0 = Yf + ((size_t)b * M + mr0) * N_TOK + j0 + 2 * tg;
        float* y1 = Yf + ((size_t)b * M + mr1) * N_TOK + j0 + 2 * tg;
#pragma unroll
        for (int nt = 0; nt < 16; nt++) {
            float2 o0 = { acc[nt][0] + bv0, acc[nt][1] + bv0 };
            float2 o1 = { acc[nt][2] + bv1, acc[nt][3] + bv1 };
            *(float2*)(y0 + nt * 8) = o0;
            *(float2*)(y1 + nt * 8) = o1;
        }
    }
}

// ---------------------------------------------------------------------------
// Batch-fused flash attention, 96-key tiles, K/V + bias double-buffered.
// 1024 threads / 32 warps (8 per SMSP): warp = (batch bb, m16-tile mq).
// Each warp owns ONE m16 query tile -> half the register state, 2x warps
// for latency hiding. Row sums via P x ones-mma (R13-proven math).
// ---------------------------------------------------------------------------
#define JT 96
#define HPk 104
#define KV_PB (2 * 32 * HPk)
#define KVBUF_H (BATCH * KV_PB)
#define KVBUF_B (KVBUF_H * 2)
#define BP 104
#define BIAS_F (128 * BP)
#define BIAS_B (BIAS_F * 4)
#define OFF_BIAS_B (2 * KVBUF_B)
#define ATTN_SMEM (OFF_BIAS_B + 2 * BIAS_B)
#define NTILES (N_TOK / JT)

__global__ __launch_bounds__(1024, 1)
void attn_mma(const __half* __restrict__ qkvh, const float* __restrict__ posb,
              __half* __restrict__ aoh)
{
    extern __shared__ __align__(16) uint16_t sH[];

    const int h = blockIdx.y, i0 = blockIdx.x * 128;
    const int tid  = threadIdx.x;
    const int lane = tid & 31, warp = tid >> 5;
    const int bb = warp & 3, mq = warp >> 2;      // mq in 0..7
    const int g = lane >> 2, tg = lane & 3;

    const uint32_t smem_u32 = (uint32_t)__cvta_generic_to_shared(sH);

    const uint16_t* qh = (const uint16_t*)(qkvh + ((size_t)bb * 3 * HIDDEN + h * DHEAD) * N_TOK);
    const __half* kvbase = qkvh + (size_t)h * DHEAD * N_TOK;
    const float* pbase = posb + (size_t)h * N_TOK * N_TOK;

    const int row0 = 16 * mq + g;                 // q-row within 128-tile
    const int gi = i0 + row0;

    // Q A-fragments (q pre-scaled by QSCALE*log2e in gmem)
    uint32_t qa[2][4];
#pragma unroll
    for (int kc = 0; kc < 2; kc++) {
        int d0 = kc * 16 + 2 * tg;
#pragma unroll
        for (int q = 0; q < 4; q++) {
            int dd = d0 + (q >> 1) * 8;
            int ii = gi + (q & 1) * 8;
            qa[kc][q] = (uint32_t)qh[(size_t)dd * N_TOK + ii]
                      | ((uint32_t)qh[(size_t)(dd + 1) * N_TOK + ii] << 16);
        }
    }

    float o[4][4];
#pragma unroll
    for (int dn = 0; dn < 4; dn++)
#pragma unroll
        for (int c = 0; c < 4; c++) o[dn][c] = 0.f;
    float ls[4] = {0.f, 0.f, 0.f, 0.f};

    // staging: 3072 KV cpa16 + 3072 bias cpa16 per tile, 3 each per thread
#define STAGE_TILE(jcol, bufsel)                                               \
    {                                                                          \
        const uint32_t kvb = (uint32_t)(bufsel) * KVBUF_B;                     \
        const uint32_t bbf = (uint32_t)(bufsel) * BIAS_B;                      \
        _Pragma("unroll")                                                      \
        for (int l = 0; l < 3; l++) {                                          \
            int t = tid + l * 1024;                                            \
            int isv = t / 1536, t2 = t - isv * 1536;                           \
            int bbs = t2 / 384, r = t2 - bbs * 384;                            \
            int d = r / 12, ch = r - d * 12;                                   \
            const __half* src = kvbase                                         \
                + ((size_t)(bbs * 3 + 1 + isv) * HIDDEN + d) * N_TOK           \
                + (jcol) + ch * 8;                                             \
            uint32_t dst = smem_u32 + kvb                                      \
                + (uint32_t)(bbs * KV_PB + isv * 32 * HPk + d * HPk + ch * 8) * 2; \
            cpa16(dst, src);                                                   \
        }                                                                      \
        _Pragma("unroll")                                                      \
        for (int l = 0; l < 3; l++) {                                          \
            int t = tid + l * 1024;                                            \
            int row = t / 24, ch = t - row * 24;                               \
            cpa16(smem_u32 + OFF_BIAS_B + bbf + (uint32_t)(row * BP + ch * 4) * 4, \
                  pbase + (size_t)(i0 + row) * N_TOK + (jcol) + ch * 4);       \
        }                                                                      \
        cpa_commit();                                                          \
    }

    STAGE_TILE(0, 0)

    for (int jt = 0; jt < NTILES; jt++) {
        cpa_wait0();
        __syncthreads();

        if (jt + 1 < NTILES)
            STAGE_TILE((jt + 1) * JT, (jt + 1) & 1)

        const int cur = jt & 1;
        const uint16_t* sVh = sH + cur * KVBUF_H + bb * KV_PB + 32 * HPk;
        const uint32_t kaddr0 = smem_u32 + (uint32_t)cur * KVBUF_B
                              + (uint32_t)bb * (KV_PB * 2) + (uint32_t)lane * (HPk * 2);
        const float* sB = (const float*)((char*)sH + OFF_BIAS_B + cur * BIAS_B);

#pragma unroll
        for (int ntp = 0; ntp < 6; ntp++) {
            uint32_t pa[4];
#pragma unroll
            for (int half = 0; half < 2; half++) {
                const int nt = 2 * ntp + half;
                uint32_t kf[4];
                ldmx4t(kf, kaddr0 + (uint32_t)nt * 16);
                float2 x0 = *(const float2*)&sB[row0 * BP + nt * 8 + 2 * tg];
                float2 x1 = *(const float2*)&sB[(row0 + 8) * BP + nt * 8 + 2 * tg];
                float c[4] = { x0.x * LOG2E, x0.y * LOG2E, x1.x * LOG2E, x1.y * LOG2E };
                mma_f16(c, qa[0], kf[0], kf[1]);
                mma_f16(c, qa[1], kf[2], kf[3]);
                pa[2 * half]     = ex2h2(h2pk(c[0], c[1]));
                pa[2 * half + 1] = ex2h2(h2pk(c[2], c[3]));
            }
#pragma unroll
            for (int dn = 0; dn < 4; dn++) {
                uint32_t b0 = *(const uint32_t*)&sVh[(dn * 8 + g) * HPk + ntp * 16 + 2 * tg];
                uint32_t b1 = *(const uint32_t*)&sVh[(dn * 8 + g) * HPk + ntp * 16 + 8 + 2 * tg];
                mma_f16(o[dn], pa, b0, b1);
            }
            mma_f16(ls, pa, ONES2, ONES2);
        }
    }
    __syncthreads();

    // ---- epilogue: normalize (l from ones-mma), stage, store fp16 ----
    float* sO = (float*)sH;   // [batch][128][33] f32 = 67584 B
    {
        float inv0 = 1.f / ls[0];
        float inv1 = 1.f / ls[2];
        float* sOb = sO + bb * (128 * 33);
#pragma unroll
        for (int dn = 0; dn < 4; dn++) {
            int dcol = dn * 8 + 2 * tg;
            sOb[row0       * 33 + dcol]     = o[dn][0] * inv0;
            sOb[row0       * 33 + dcol + 1] = o[dn][1] * inv0;
            sOb[(row0 + 8) * 33 + dcol]     = o[dn][2] * inv1;
            sOb[(row0 + 8) * 33 + dcol + 1] = o[dn][3] * inv1;
        }
    }
    __syncthreads();
#pragma unroll
    for (int t = tid; t < 8192; t += 1024) {
        int bbs = t >> 11, r = t & 2047;
        int d = r >> 6, ii2 = (r & 63) * 2;
        const float* s = sO + bbs * (128 * 33);
        uint32_t pk = h2pk(s[ii2 * 33 + d], s[(ii2 + 1) * 33 + d]);
        *(uint32_t*)&aoh[((size_t)bbs * HIDDEN + h * DHEAD + d) * N_TOK + i0 + ii2] = pk;
    }
}

// ---------------------------------------------------------------------------
extern "C" void kernel_launch(void* const* d_in, const int* in_sizes, int n_in,
                              void* d_out, int out_size)
{
    const float* x        = (const float*)d_in[0];
    const float* pos_bias = (const float*)d_in[1];
    const float* w_qkv    = (const float*)d_in[2];
    const float* w_out    = (const float*)d_in[3];
    const float* b_out    = (const float*)d_in[4];
    float* out = (float*)d_out;

    __half *xh, *wqkvh, *wouth, *qkvh, *aoh;
    cudaGetSymbolAddress((void**)&xh,    g_xh);
    cudaGetSymbolAddress((void**)&wqkvh, g_wqkvh);
    cudaGetSymbolAddress((void**)&wouth, g_wouth);
    cudaGetSymbolAddress((void**)&qkvh,  g_qkvh);
    cudaGetSymbolAddress((void**)&aoh,   g_aoh);

    cudaFuncSetAttribute(attn_mma, cudaFuncAttributeMaxDynamicSharedMemorySize, ATTN_SMEM);

    const int n0 = BATCH * 256 * N_TOK;
    const int n1 = 3 * HIDDEN * 256;
    const int n2 = HIDDEN * 256;
    const int tot4 = (n0 + n1 + n2) / 4;
    f2h3<<<(tot4 + 255) / 256, 256>>>(x, xh, n0, w_qkv, wqkvh, n1, w_out, wouth, n2);

    dim3 gA(N_TOK / 128, (3 * HIDDEN) / 128, BATCH);
    gemm_h<<<gA, dim3(256)>>>(wqkvh, xh, qkvh, 3 * HIDDEN, nullptr, 1, 1);

    dim3 gB(N_TOK / 128, HEADS);
    attn_mma<<<gB, dim3(1024), ATTN_SMEM>>>(qkvh, pos_bias, aoh);

    dim3 gC(N_TOK / 128, HIDDEN / 128, BATCH);
    gemm_h<<<gC, dim3(256)>>>(wouth, aoh, out, HIDDEN, b_out, 0, 0);
}

// round 16
// speedup vs baseline: 1.0847x; 1.0847x over previous
#include <cuda_runtime.h>
#include <cuda_fp16.h>
#include <cstdint>

#define N_TOK 2304
#define BATCH 4
#define HEADS 8
#define DHEAD 32
#define HIDDEN 256
#define QSCALE 0.17677669529663689f  // 32^-0.5
#define LOG2E  1.4426950408889634f
#define ONES2  0x3C003C00u           // f16x2 (1.0, 1.0)

// ---- fp16 helpers ----
__device__ __forceinline__ uint32_t h2pk(float lo, float hi) {
    uint32_t r; asm("cvt.rn.f16x2.f32 %0,%1,%2;" : "=r"(r) : "f"(hi), "f"(lo)); return r;
}
__device__ __forceinline__ uint32_t ex2h2(uint32_t x) {
    uint32_t r; asm("ex2.approx.f16x2 %0,%1;" : "=r"(r) : "r"(x)); return r;
}
__device__ __forceinline__ void mma_f16(float c[4], const uint32_t a[4],
                                        uint32_t b0, uint32_t b1) {
    asm("mma.sync.aligned.m16n8k16.row.col.f32.f16.f16.f32 "
        "{%0,%1,%2,%3},{%4,%5,%6,%7},{%8,%9},{%0,%1,%2,%3};"
        : "+f"(c[0]), "+f"(c[1]), "+f"(c[2]), "+f"(c[3])
        : "r"(a[0]), "r"(a[1]), "r"(a[2]), "r"(a[3]), "r"(b0), "r"(b1));
}
__device__ __forceinline__ void ldmx4t(uint32_t r[4], uint32_t addr) {
    asm volatile("ldmatrix.sync.aligned.m8n8.x4.trans.shared.b16 {%0,%1,%2,%3},[%4];"
                 : "=r"(r[0]), "=r"(r[1]), "=r"(r[2]), "=r"(r[3]) : "r"(addr));
}

// ---- cp.async helpers ----
__device__ __forceinline__ void cpa16(uint32_t smem_dst, const void* gsrc) {
    asm volatile("cp.async.cg.shared.global [%0],[%1],16;" :: "r"(smem_dst), "l"(gsrc));
}
__device__ __forceinline__ void cpa_commit() { asm volatile("cp.async.commit_group;"); }
__device__ __forceinline__ void cpa_wait1()  { asm volatile("cp.async.wait_group 1;"); }
__device__ __forceinline__ void cpa_wait0()  { asm volatile("cp.async.wait_group 0;"); }

// Scratch (alloc-free rule: __device__ globals)
__device__ __half g_xh   [BATCH * 256 * N_TOK];          // fp16 x
__device__ __half g_wqkvh[3 * HIDDEN * 256];             // fp16 w_qkv
__device__ __half g_wouth[HIDDEN * 256];                 // fp16 w_out
__device__ __half g_qkvh [BATCH * 3 * HIDDEN * N_TOK];   // fp16 qkv
__device__ __half g_aoh  [BATCH * HIDDEN * N_TOK];       // fp16 attn out

// ---------------------------------------------------------------------------
// f32 -> f16 conversion for x, w_qkv, w_out (single launch)
// ---------------------------------------------------------------------------
__global__ __launch_bounds__(256)
void f2h3(const float* __restrict__ a0, __half* __restrict__ o0, int n0,
          const float* __restrict__ a1, __half* __restrict__ o1, int n1,
          const float* __restrict__ a2, __half* __restrict__ o2, int n2)
{
    int i = (blockIdx.x * 256 + threadIdx.x) * 4;
    const float* src; __half* dst;
    if (i < n0)            { src = a0 + i;           dst = o0 + i; }
    else if (i < n0 + n1)  { src = a1 + (i - n0);    dst = o1 + (i - n0); }
    else if (i < n0 + n1 + n2) { src = a2 + (i - n0 - n1); dst = o2 + (i - n0 - n1); }
    else return;
    float4 v = *(const float4*)src;
    *(uint2*)dst = make_uint2(h2pk(v.x, v.y), h2pk(v.z, v.w));
}

// ---------------------------------------------------------------------------
// all-fp16 GEMM (R14-proven): 128m x 128j CTA tile, K in 8 chunks of 32,
// cp.async double-buffered, W A-fragments prefetched one chunk ahead.
// ---------------------------------------------------------------------------
#define HPG 136

__global__ __launch_bounds__(256)
void gemm_h(const __half* __restrict__ W, const __half* __restrict__ X,
            void* __restrict__ Yv, int M,
            const float* __restrict__ bias, int qscale, int out_half)
{
    __shared__ __align__(16) uint16_t sX[2][32 * HPG];

    const int b  = blockIdx.z;
    const int m0 = blockIdx.y * 128;
    const int j0 = blockIdx.x * 128;
    const int tid = threadIdx.x;
    const int lane = tid & 31, warp = tid >> 5;
    const int g = lane >> 2, tg = lane & 3;
    const int mw = m0 + 16 * warp;

    const __half* Xb = X + (size_t)b * 256 * N_TOK;
    const uint32_t sbase = (uint32_t)__cvta_generic_to_shared(sX);

    int skk[2], sj8[2];
#pragma unroll
    for (int l = 0; l < 2; l++) {
        int t = tid + l * 256;
        skk[l] = t >> 4; sj8[l] = (t & 15) * 8;
    }

    float acc[16][4];
#pragma unroll
    for (int nt = 0; nt < 16; nt++)
#pragma unroll
        for (int c = 0; c < 4; c++) acc[nt][c] = 0.f;

#pragma unroll
    for (int l = 0; l < 2; l++)
        cpa16(sbase + (uint32_t)(skk[l] * HPG + sj8[l]) * 2,
              Xb + (size_t)skk[l] * N_TOK + j0 + sj8[l]);
    cpa_commit();

    uint32_t aw[2][4];
#pragma unroll
    for (int kc = 0; kc < 2; kc++) {
        const __half* wr = W + (size_t)(mw + g) * 256 + kc * 16;
        aw[kc][0] = *(const uint32_t*)(wr + 2 * tg);
        aw[kc][1] = *(const uint32_t*)(wr + 8 * 256 + 2 * tg);
        aw[kc][2] = *(const uint32_t*)(wr + 2 * tg + 8);
        aw[kc][3] = *(const uint32_t*)(wr + 8 * 256 + 2 * tg + 8);
    }

    for (int c = 0; c < 8; c++) {
        if (c > 0) __syncthreads();
        if (c + 1 < 8) {
            const int kn = (c + 1) * 32;
            const uint32_t boff = (uint32_t)(((c + 1) & 1) * 32 * HPG) * 2;
#pragma unroll
            for (int l = 0; l < 2; l++)
                cpa16(sbase + boff + (uint32_t)(skk[l] * HPG + sj8[l]) * 2,
                      Xb + (size_t)(kn + skk[l]) * N_TOK + j0 + sj8[l]);
            cpa_commit();
        }

        uint32_t an[2][4];
        if (c + 1 < 8) {
#pragma unroll
            for (int kc = 0; kc < 2; kc++) {
                const __half* wr = W + (size_t)(mw + g) * 256 + (c + 1) * 32 + kc * 16;
                an[kc][0] = *(const uint32_t*)(wr + 2 * tg);
                an[kc][1] = *(const uint32_t*)(wr + 8 * 256 + 2 * tg);
                an[kc][2] = *(const uint32_t*)(wr + 2 * tg + 8);
                an[kc][3] = *(const uint32_t*)(wr + 8 * 256 + 2 * tg + 8);
            }
        }

        if (c + 1 < 8) cpa_wait1(); else cpa_wait0();
        __syncthreads();

        const uint32_t xaddr0 = sbase + (uint32_t)((c & 1) * 32 * HPG + lane * HPG) * 2;
#pragma unroll
        for (int nt = 0; nt < 16; nt++) {
            uint32_t kf[4];
            ldmx4t(kf, xaddr0 + (uint32_t)nt * 16);
            mma_f16(acc[nt], aw[0], kf[0], kf[1]);
            mma_f16(acc[nt], aw[1], kf[2], kf[3]);
        }
        if (c + 1 < 8) {
#pragma unroll
            for (int kc = 0; kc < 2; kc++)
#pragma unroll
                for (int q = 0; q < 4; q++) aw[kc][q] = an[kc][q];
        }
    }

    const int mr0 = mw + g, mr1 = mw + g + 8;
    if (out_half) {
        const float qs = QSCALE * LOG2E;
        const float s0 = (qscale && mr0 < HIDDEN) ? qs : 1.f;
        const float s1 = (qscale && mr1 < HIDDEN) ? qs : 1.f;
        __half* Yh = (__half*)Yv;
        __half* y0 = Yh + ((size_t)b * M + mr0) * N_TOK + j0 + 2 * tg;
        __half* y1 = Yh + ((size_t)b * M + mr1) * N_TOK + j0 + 2 * tg;
#pragma unroll
        for (int nt = 0; nt < 16; nt++) {
            *(uint32_t*)(y0 + nt * 8) = h2pk(acc[nt][0] * s0, acc[nt][1] * s0);
            *(uint32_t*)(y1 + nt * 8) = h2pk(acc[nt][2] * s1, acc[nt][3] * s1);
        }
    } else {
        float* Yf = (float*)Yv;
        const float bv0 = bias ? bias[mr0] : 0.f;
        const float bv1 = bias ? bias[mr1] : 0.f;
        float* y0 = Yf + ((size_t)b * M + mr0) * N_TOK + j0 + 2 * tg;
        float* y1 = Yf + ((size_t)b * M + mr1) * N_TOK + j0 + 2 * tg;
#pragma unroll
        for (int nt = 0; nt < 16; nt++) {
            float2 o0 = { acc[nt][0] + bv0, acc[nt][1] + bv0 };
            float2 o1 = { acc[nt][2] + bv1, acc[nt][3] + bv1 };
            *(float2*)(y0 + nt * 8) = o0;
            *(float2*)(y1 + nt * 8) = o1;
        }
    }
}

// ---------------------------------------------------------------------------
// Batch-fused flash attention (exact R13-best): 512 threads, 96-key tiles,
// K/V + bias double-buffered cp.async, fp16 mma, base-2 softmax (ex2.f16x2),
// row sums via P x ones-mma.
// ---------------------------------------------------------------------------
#define JT 96
#define HPk 104
#define KV_PB (2 * 32 * HPk)
#define KVBUF_H (BATCH * KV_PB)
#define KVBUF_B (KVBUF_H * 2)
#define BP 104
#define BIAS_F (128 * BP)
#define BIAS_B (BIAS_F * 4)
#define OFF_BIAS_B (2 * KVBUF_B)
#define ATTN_SMEM (OFF_BIAS_B + 2 * BIAS_B)
#define NTILES (N_TOK / JT)

__global__ __launch_bounds__(512, 1)
void attn_mma(const __half* __restrict__ qkvh, const float* __restrict__ posb,
              __half* __restrict__ aoh)
{
    extern __shared__ __align__(16) uint16_t sH[];

    const int h = blockIdx.y, i0 = blockIdx.x * 128;
    const int tid  = threadIdx.x;
    const int lane = tid & 31, warp = tid >> 5;
    const int bb = warp & 3, mt = warp >> 2;
    const int g = lane >> 2, tg = lane & 3;

    const uint32_t smem_u32 = (uint32_t)__cvta_generic_to_shared(sH);
    const uint32_t bias_u32 = smem_u32 + OFF_BIAS_B;

    const uint16_t* qh = (const uint16_t*)(qkvh + ((size_t)bb * 3 * HIDDEN + h * DHEAD) * N_TOK);
    const __half* kvbase = qkvh + (size_t)h * DHEAD * N_TOK;
    const float* pbase = posb + (size_t)h * N_TOK * N_TOK;

    const int gi0 = i0 + 32 * mt + g;

    uint32_t qa[2][2][4];
#pragma unroll
    for (int rt = 0; rt < 2; rt++) {
        const int gi = gi0 + 16 * rt;
#pragma unroll
        for (int kc = 0; kc < 2; kc++) {
            int d0 = kc * 16 + 2 * tg;
#pragma unroll
            for (int q = 0; q < 4; q++) {
                int dd = d0 + (q >> 1) * 8;
                int ii = gi + (q & 1) * 8;
                qa[rt][kc][q] = (uint32_t)qh[(size_t)dd * N_TOK + ii]
                              | ((uint32_t)qh[(size_t)(dd + 1) * N_TOK + ii] << 16);
            }
        }
    }

    float o[2][4][4];
#pragma unroll
    for (int rt = 0; rt < 2; rt++)
#pragma unroll
        for (int dn = 0; dn < 4; dn++)
#pragma unroll
            for (int c = 0; c < 4; c++) o[rt][dn][c] = 0.f;
    float ls[2][4];
#pragma unroll
    for (int rt = 0; rt < 2; rt++)
#pragma unroll
        for (int c = 0; c < 4; c++) ls[rt][c] = 0.f;

#define STAGE_TILE(jcol, bufsel)                                               \
    {                                                                          \
        const uint32_t kvb = (uint32_t)(bufsel) * KVBUF_B;                     \
        const uint32_t bbf = (uint32_t)(bufsel) * BIAS_B;                      \
        _Pragma("unroll")                                                      \
        for (int l = 0; l < 6; l++) {                                          \
            int t = tid + l * 512;                                             \
            int isv = t / 1536, t2 = t - isv * 1536;                           \
            int bbs = t2 / 384, r = t2 - bbs * 384;                            \
            int d = r / 12, ch = r - d * 12;                                   \
            const __half* src = kvbase                                         \
                + ((size_t)(bbs * 3 + 1 + isv) * HIDDEN + d) * N_TOK           \
                + (jcol) + ch * 8;                                             \
            uint32_t dst = smem_u32 + kvb                                      \
                + (uint32_t)(bbs * KV_PB + isv * 32 * HPk + d * HPk + ch * 8) * 2; \
            cpa16(dst, src);                                                   \
        }                                                                      \
        _Pragma("unroll")                                                      \
        for (int l = 0; l < 6; l++) {                                          \
            int t = tid + l * 512;                                             \
            int row = t / 24, ch = t - row * 24;                               \
            cpa16(bias_u32 + bbf + (uint32_t)(row * BP + ch * 4) * 4,          \
                  pbase + (size_t)(i0 + row) * N_TOK + (jcol) + ch * 4);       \
        }                                                                      \
        cpa_commit();                                                          \
    }

    STAGE_TILE(0, 0)

    for (int jt = 0; jt < NTILES; jt++) {
        cpa_wait0();
        __syncthreads();

        if (jt + 1 < NTILES)
            STAGE_TILE((jt + 1) * JT, (jt + 1) & 1)

        const int cur = jt & 1;
        const uint16_t* sVh = sH + cur * KVBUF_H + bb * KV_PB + 32 * HPk;
        const uint32_t kaddr0 = smem_u32 + (uint32_t)cur * KVBUF_B
                              + (uint32_t)bb * (KV_PB * 2) + (uint32_t)lane * (HPk * 2);
        const float* sB = (const float*)((char*)sH + OFF_BIAS_B + cur * BIAS_B);

#pragma unroll
        for (int ntp = 0; ntp < 6; ntp++) {
            uint32_t pa[2][4];
#pragma unroll
            for (int half = 0; half < 2; half++) {
                const int nt = 2 * ntp + half;
                uint32_t kf[4];
                ldmx4t(kf, kaddr0 + (uint32_t)nt * 16);
#pragma unroll
                for (int rt = 0; rt < 2; rt++) {
                    const int row0 = 32 * mt + 16 * rt + g;
                    float2 x0 = *(const float2*)&sB[row0 * BP + nt * 8 + 2 * tg];
                    float2 x1 = *(const float2*)&sB[(row0 + 8) * BP + nt * 8 + 2 * tg];
                    float c[4] = { x0.x * LOG2E, x0.y * LOG2E, x1.x * LOG2E, x1.y * LOG2E };
                    mma_f16(c, qa[rt][0], kf[0], kf[1]);
                    mma_f16(c, qa[rt][1], kf[2], kf[3]);
                    pa[rt][2 * half]     = ex2h2(h2pk(c[0], c[1]));
                    pa[rt][2 * half + 1] = ex2h2(h2pk(c[2], c[3]));
                }
            }
#pragma unroll
            for (int dn = 0; dn < 4; dn++) {
                uint32_t b0 = *(const uint32_t*)&sVh[(dn * 8 + g) * HPk + ntp * 16 + 2 * tg];
                uint32_t b1 = *(const uint32_t*)&sVh[(dn * 8 + g) * HPk + ntp * 16 + 8 + 2 * tg];
                mma_f16(o[0][dn], pa[0], b0, b1);
                mma_f16(o[1][dn], pa[1], b0, b1);
            }
            mma_f16(ls[0], pa[0], ONES2, ONES2);
            mma_f16(ls[1], pa[1], ONES2, ONES2);
        }
    }
    __syncthreads();

    // ---- epilogue: normalize (l from ones-mma), stage, store fp16 ----
    float* sO = (float*)sH;   // [batch][128][33] f32 = 67584 B
#pragma unroll
    for (int rt = 0; rt < 2; rt++) {
        float inv0 = 1.f / ls[rt][0];
        float inv1 = 1.f / ls[rt][2];
        int row0 = 32 * mt + 16 * rt + g;
        float* sOb = sO + bb * (128 * 33);
#pragma unroll
        for (int dn = 0; dn < 4; dn++) {
            int dcol = dn * 8 + 2 * tg;
            sOb[row0       * 33 + dcol]     = o[rt][dn][0] * inv0;
            sOb[row0       * 33 + dcol + 1] = o[rt][dn][1] * inv0;
            sOb[(row0 + 8) * 33 + dcol]     = o[rt][dn][2] * inv1;
            sOb[(row0 + 8) * 33 + dcol + 1] = o[rt][dn][3] * inv1;
        }
    }
    __syncthreads();
#pragma unroll
    for (int t = tid; t < 8192; t += 512) {
        int bbs = t >> 11, r = t & 2047;
        int d = r >> 6, ii2 = (r & 63) * 2;
        const float* s = sO + bbs * (128 * 33);
        uint32_t pk = h2pk(s[ii2 * 33 + d], s[(ii2 + 1) * 33 + d]);
        *(uint32_t*)&aoh[((size_t)bbs * HIDDEN + h * DHEAD + d) * N_TOK + i0 + ii2] = pk;
    }
}

// ---------------------------------------------------------------------------
extern "C" void kernel_launch(void* const* d_in, const int* in_sizes, int n_in,
                              void* d_out, int out_size)
{
    const float* x        = (const float*)d_in[0];
    const float* pos_bias = (const float*)d_in[1];
    const float* w_qkv    = (const float*)d_in[2];
    const float* w_out    = (const float*)d_in[3];
    const float* b_out    = (const float*)d_in[4];
    float* out = (float*)d_out;

    __half *xh, *wqkvh, *wouth, *qkvh, *aoh;
    cudaGetSymbolAddress((void**)&xh,    g_xh);
    cudaGetSymbolAddress((void**)&wqkvh, g_wqkvh);
    cudaGetSymbolAddress((void**)&wouth, g_wouth);
    cudaGetSymbolAddress((void**)&qkvh,  g_qkvh);
    cudaGetSymbolAddress((void**)&aoh,   g_aoh);

    cudaFuncSetAttribute(attn_mma, cudaFuncAttributeMaxDynamicSharedMemorySize, ATTN_SMEM);

    const int n0 = BATCH * 256 * N_TOK;
    const int n1 = 3 * HIDDEN * 256;
    const int n2 = HIDDEN * 256;
    const int tot4 = (n0 + n1 + n2) / 4;
    f2h3<<<(tot4 + 255) / 256, 256>>>(x, xh, n0, w_qkv, wqkvh, n1, w_out, wouth, n2);

    dim3 gA(N_TOK / 128, (3 * HIDDEN) / 128, BATCH);
    gemm_h<<<gA, dim3(256)>>>(wqkvh, xh, qkvh, 3 * HIDDEN, nullptr, 1, 1);

    dim3 gB(N_TOK / 128, HEADS);
    attn_mma<<<gB, dim3(512), ATTN_SMEM>>>(qkvh, pos_bias, aoh);

    dim3 gC(N_TOK / 128, HIDDEN / 128, BATCH);
    gemm_h<<<gC, dim3(256)>>>(wouth, aoh, out, HIDDEN, b_out, 0, 0);
}